// round 13
// baseline (speedup 1.0000x reference)
#include <cuda_runtime.h>
#include <cooperative_groups.h>
#include <cstdint>

namespace cg = cooperative_groups;

#define IN_NODES  1152
#define OUT_NODES 10
#define IN_DIM    8
#define OUT_DIM   16
#define BATCH     256
#define COLS      160
#define KTOT      (IN_NODES * IN_DIM)     // 9216
#define ISPLIT    144
#define CPB       8
#define NTHR      512

typedef unsigned long long u64;

#define FMA2(acc, a, b) asm("fma.rn.f32x2 %0, %1, %2, %0;" : "+l"(acc) : "l"(a), "l"(b))

__device__ __forceinline__ float f2sum(u64 d) {
    float lo, hi;
    asm("mov.b64 {%0,%1}, %2;" : "=f"(lo), "=f"(hi) : "l"(d));
    return lo + hi;
}
__device__ __forceinline__ u64 fpack(float lo, float hi) {
    u64 p;
    asm("mov.b64 %0, {%1,%2};" : "=l"(p) : "f"(lo), "f"(hi));
    return p;
}
__device__ __forceinline__ void cpa16(uint32_t dst, const float* src) {
    asm volatile("cp.async.cg.shared.global [%0], [%1], 16;" :: "r"(dst), "l"(src));
}
#define CPA_COMMIT() asm volatile("cp.async.commit_group;")

// ---------------- device scratch ----------------
__device__ float g_xT   [KTOT * BATCH];            // x transposed [ik][b]
__device__ float g_spart[ISPLIT * COLS * BATCH];   // s partials [grp][col][b]
__device__ float g_vT2  [COLS * BATCH];            // v col-major [col][b]
__device__ float g_b    [IN_NODES * OUT_NODES];    // routing logits
__device__ float g_cs   [IN_NODES * OUT_NODES];    // softmax coefficients

// fA smem float offsets (double-buffered)
#define VS0 0
#define XS0 10880
#define VS1 14976
#define XS1 25856
#define SMEM_A_FL 29952

// =================== bodies (shared by persistent + fallback) ===================

// transpose x [256][9216] -> xT [9216][256]; 2304 tiles of 32x32, 16 per block
__device__ __forceinline__ void transpose_body(float* sm, const float* __restrict__ x,
                                               int bid, int tid) {
    const int tx = tid & 31, r = tid >> 5;   // r 0..15
    for (int t = bid; t < 2304; t += ISPLIT) {
        int ik0 = (t % 288) * 32;
        int b0  = (t / 288) * 32;
        sm[r * 33 + tx]        = x[(size_t)(b0 + r) * KTOT + ik0 + tx];
        sm[(r + 16) * 33 + tx] = x[(size_t)(b0 + r + 16) * KTOT + ik0 + tx];
        __syncthreads();
        g_xT[(size_t)(ik0 + r) * BATCH + b0 + tx]        = sm[tx * 33 + r];
        g_xT[(size_t)(ik0 + r + 16) * BATCH + b0 + tx]   = sm[tx * 33 + r + 16];
        __syncthreads();
    }
}

// stage one fA chunk (64 b): vs[160][68] + xs[64][64], 3584 x cp.async.16
__device__ __forceinline__ void stageA(int cb, uint32_t vsa, uint32_t xsa, int i0, int tid) {
    const int b0 = cb * 64;
    for (int it = tid; it < 3584; it += NTHR) {
        if (it < 2560) {
            int col = it >> 4, q = (it & 15) << 2;
            cpa16(vsa + (col * 68 + q) * 4, g_vT2 + col * BATCH + b0 + q);
        } else {
            int r = it - 2560;
            int row = r >> 4, q = (r & 15) << 2;
            cpa16(xsa + (row * 64 + q) * 4, g_xT + ((size_t)(i0 * 8) + row) * BATCH + b0 + q);
        }
    }
    CPA_COMMIT();
}

// fA: T-GEMM + W-contraction -> b-update + softmax -> g_cs
__device__ __forceinline__ void fA_body(float* sm, const float* __restrict__ W,
                                        int mode, int i0, int tid) {
    __shared__ float bsA[2][80];
    __shared__ float brow[80];
    const uint32_t smb = (uint32_t)__cvta_generic_to_shared(sm);

    const int w = tid >> 5, lane = tid & 31;
    const int ic = w & 7, bh = w >> 3;

    u64 acc2[8][5];
#pragma unroll
    for (int kk = 0; kk < 8; ++kk)
#pragma unroll
        for (int cc = 0; cc < 5; ++cc) acc2[kk][cc] = 0ULL;

    stageA(0, smb + VS0 * 4, smb + XS0 * 4, i0, tid);
    stageA(1, smb + VS1 * 4, smb + XS1 * 4, i0, tid);

#pragma unroll
    for (int cb = 0; cb < 4; ++cb) {
        if (cb < 3) asm volatile("cp.async.wait_group 1;");
        else        asm volatile("cp.async.wait_group 0;");
        __syncthreads();

        const float* vsb = sm + ((cb & 1) ? VS1 : VS0);
        const float* xsb = sm + ((cb & 1) ? XS1 : XS0);
        const float* vbase = vsb + lane * 68 + bh * 32;
        const float* xbase = xsb + ic * 512 + bh * 32;

#pragma unroll
        for (int b4 = 0; b4 < 8; ++b4) {
            ulonglong2 vvx[5];
#pragma unroll
            for (int cc = 0; cc < 5; ++cc)
                vvx[cc] = *(const ulonglong2*)(vbase + cc * 2176 + 4 * b4);
#pragma unroll
            for (int kk = 0; kk < 8; ++kk) {
                ulonglong2 xv = *(const ulonglong2*)(xbase + kk * 64 + 4 * b4);
#pragma unroll
                for (int cc = 0; cc < 5; ++cc) {
                    FMA2(acc2[kk][cc], xv.x, vvx[cc].x);
                    FMA2(acc2[kk][cc], xv.y, vvx[cc].y);
                }
            }
        }

        if (cb < 2) {
            __syncthreads();
            stageA(cb + 2, smb + ((cb & 1) ? VS1 : VS0) * 4,
                           smb + ((cb & 1) ? XS1 : XS0) * 4, i0, tid);
        }
    }

#pragma unroll
    for (int cc = 0; cc < 5; ++cc) {
        int col = cc * 32 + lane;
        const float4* w4 = (const float4*)(W + ((size_t)(i0 + ic) * 160 + col) * 8);
        float4 wa = w4[0], wb = w4[1];
        float p = wa.x * f2sum(acc2[0][cc]) + wa.y * f2sum(acc2[1][cc])
                + wa.z * f2sum(acc2[2][cc]) + wa.w * f2sum(acc2[3][cc])
                + wb.x * f2sum(acc2[4][cc]) + wb.y * f2sum(acc2[5][cc])
                + wb.z * f2sum(acc2[6][cc]) + wb.w * f2sum(acc2[7][cc]);
#pragma unroll
        for (int off = 8; off; off >>= 1)
            p += __shfl_xor_sync(0xffffffffu, p, off, 16);
        if ((lane & 15) == 0)
            bsA[bh][ic * 10 + cc * 2 + (lane >> 4)] = p;
    }
    __syncthreads();

    if (tid < 80) {
        float bn = (bsA[0][tid] + bsA[1][tid]) * (1.0f / (float)BATCH);
        if (mode == 2) bn += g_b[i0 * OUT_NODES + tid];
        g_b[i0 * OUT_NODES + tid] = bn;
        brow[tid] = bn;
    }
    __syncthreads();
    if (tid < 8) {
        float m = -1e30f;
#pragma unroll
        for (int j = 0; j < 10; ++j) m = fmaxf(m, brow[tid * 10 + j]);
        float e[10], s = 0.0f;
#pragma unroll
        for (int j = 0; j < 10; ++j) { e[j] = __expf(brow[tid * 10 + j] - m); s += e[j]; }
        float inv = 1.0f / s;
#pragma unroll
        for (int j = 0; j < 10; ++j) g_cs[(i0 + tid) * OUT_NODES + j] = e[j] * inv;
    }
}

// prefetch one fB chunk into regs (k-pair packing)
__device__ __forceinline__ void loadB(u64* pf, int ch, int i0, int tid) {
    const int b0 = ch * 64;
#pragma unroll
    for (int r = 0; r < 4; ++r) {
        int it = tid + NTHR * r;
        int ic2 = it >> 8, kp = (it >> 6) & 3, b = it & 63;
        const float* gp = g_xT + ((size_t)(i0 + ic2) * 8 + 2 * kp) * BATCH + b0 + b;
        pf[r] = fpack(gp[0], gp[BATCH]);
    }
}

// fB: s-GEMM -> spart
__device__ __forceinline__ void fB_body(float* sm, const float* __restrict__ W,
                                        int first, int i0, int tid, int bid) {
    __shared__ float cs_sh[80];
    if (!first && tid < 80)
        cs_sh[tid] = g_cs[i0 * OUT_NODES + tid];

    float* ws = sm;                     // [8 ic][160 col][8 k] scaled W
    u64*   xb = (u64*)(sm + 10240);     // [8 ic][4 kp][64 b]
    const int tx = tid & 15;
    const int ty = tid >> 4;            // 0..31, 5 cols each

    u64 pf[4];
    loadB(pf, 0, i0, tid);

    for (int ch = 0; ch < 4; ++ch) {
        const int b0 = ch * 64;
        __syncthreads();
        if (ch == 0) {
            const float4* W4 = (const float4*)(W + (size_t)i0 * 1280);
            float4* ws4 = (float4*)ws;
            for (int q = tid; q < 2560; q += NTHR) {
                int ic2 = q / 320, r = q - ic2 * 320;
                float c = first ? 0.1f : cs_sh[ic2 * 10 + (r >> 5)];
                float4 wv = W4[q];
                ws4[q] = make_float4(wv.x * c, wv.y * c, wv.z * c, wv.w * c);
            }
        }
#pragma unroll
        for (int r = 0; r < 4; ++r)
            xb[tid + NTHR * r] = pf[r];
        __syncthreads();
        if (ch < 3) loadB(pf, ch + 1, i0, tid);

        u64 accB[4][5];
#pragma unroll
        for (int q = 0; q < 4; ++q)
#pragma unroll
            for (int cc = 0; cc < 5; ++cc) accB[q][cc] = 0ULL;

        const float* wrow = ws + ty * 40;
#pragma unroll 2
        for (int ic2 = 0; ic2 < CPB; ++ic2) {
#pragma unroll
            for (int kph = 0; kph < 2; ++kph) {
                ulonglong2 wx[5];
#pragma unroll
                for (int cc = 0; cc < 5; ++cc)
                    wx[cc] = *(const ulonglong2*)(wrow + ic2 * 1280 + cc * 8 + kph * 4);
#pragma unroll
                for (int kpl = 0; kpl < 2; ++kpl) {
                    const u64* xp = xb + (ic2 * 4 + kph * 2 + kpl) * 64 + tx;
                    u64 x0 = xp[0], x1 = xp[16], x2 = xp[32], x3 = xp[48];
#pragma unroll
                    for (int cc = 0; cc < 5; ++cc) {
                        u64 w2 = kpl ? wx[cc].y : wx[cc].x;
                        FMA2(accB[0][cc], x0, w2);
                        FMA2(accB[1][cc], x1, w2);
                        FMA2(accB[2][cc], x2, w2);
                        FMA2(accB[3][cc], x3, w2);
                    }
                }
            }
        }

        float* outp = g_spart + (size_t)bid * (COLS * BATCH) + b0 + tx;
#pragma unroll
        for (int cc = 0; cc < 5; ++cc) {
            int col = ty * 5 + cc;
#pragma unroll
            for (int q = 0; q < 4; ++q)
                outp[col * BATCH + 16 * q] = f2sum(accB[q][cc]);
        }
    }
}

// squash: 80 active blocks, each = (j, 32-b group); reduce 144 partials
__device__ __forceinline__ void squash_body(float* sm, float* __restrict__ out,
                                            int write_out, int bid, int tid) {
    if (bid >= 80) return;
    const int j  = bid / 8;
    const int b0 = (bid % 8) * 32;
    const int b_loc = tid & 31, d = tid >> 5;   // d 0..15

    const float* p = g_spart + (size_t)(j * 16 + d) * BATCH + b0 + b_loc;
    float s = 0.0f;
#pragma unroll 4
    for (int is = 0; is < ISPLIT; ++is)
        s += p[(size_t)is * (COLS * BATCH)];

    float* sq = sm;              // [16][33]
    float* vt = sm + 16 * 33;    // [16][33]
    sq[d * 33 + b_loc] = s * s;
    __syncthreads();
    if (d < 8) sq[d * 33 + b_loc] += sq[(d + 8) * 33 + b_loc];
    __syncthreads();
    if (d < 4) sq[d * 33 + b_loc] += sq[(d + 4) * 33 + b_loc];
    __syncthreads();
    if (d < 2) sq[d * 33 + b_loc] += sq[(d + 2) * 33 + b_loc];
    __syncthreads();
    if (d < 1) sq[b_loc] += sq[33 + b_loc];
    __syncthreads();

    float nsq = sq[b_loc];
    float coef = nsq * rsqrtf(nsq) / (1.0f + nsq);
    float v = s * coef;

    g_vT2[(size_t)(j * 16 + d) * BATCH + b0 + b_loc] = v;
    if (write_out) {
        vt[d * 33 + b_loc] = v;
        __syncthreads();
        int dn = tid & 15, bn = tid >> 4;
        out[(size_t)(b0 + bn) * COLS + j * 16 + dn] = vt[dn * 33 + bn];
    }
}

// =================== persistent cooperative kernel ===================
__global__ __launch_bounds__(NTHR, 1) void caps_persistent(
        const float* __restrict__ x, const float* __restrict__ W, float* __restrict__ out) {
    extern __shared__ float sm[];
    cg::grid_group grid = cg::this_grid();
    const int bid = blockIdx.x, tid = threadIdx.x;
    const int i0  = bid * CPB;

    transpose_body(sm, x, bid, tid);
    grid.sync();
    fB_body(sm, W, 1, i0, tid, bid);        // iter 1: c = 0.1
    grid.sync();
    squash_body(sm, out, 0, bid, tid);
    grid.sync();
    fA_body(sm, W, 1, i0, tid);             // iter 2
    grid.sync();
    fB_body(sm, W, 0, i0, tid, bid);
    grid.sync();
    squash_body(sm, out, 0, bid, tid);
    grid.sync();
    fA_body(sm, W, 2, i0, tid);             // iter 3
    grid.sync();
    fB_body(sm, W, 0, i0, tid, bid);
    grid.sync();
    squash_body(sm, out, 1, bid, tid);
}

// =================== fallback wrappers (multi-launch, R12 sequence) ===================
__global__ __launch_bounds__(NTHR) void transpose_k(const float* __restrict__ x) {
    extern __shared__ float sm[];
    transpose_body(sm, x, blockIdx.x, threadIdx.x);
}
__global__ __launch_bounds__(NTHR, 1) void fA_k(const float* __restrict__ W, int mode) {
    extern __shared__ float sm[];
    fA_body(sm, W, mode, blockIdx.x * CPB, threadIdx.x);
}
__global__ __launch_bounds__(NTHR, 1) void fB_k(const float* __restrict__ W, int first) {
    extern __shared__ float sm[];
    fB_body(sm, W, first, blockIdx.x * CPB, threadIdx.x, blockIdx.x);
}
__global__ __launch_bounds__(NTHR) void squash_k(float* __restrict__ out, int write_out) {
    extern __shared__ float sm[];
    squash_body(sm, out, write_out, blockIdx.x, threadIdx.x);
}

// ---------------- launch ----------------
extern "C" void kernel_launch(void* const* d_in, const int* in_sizes, int n_in,
                              void* d_out, int out_size) {
    const float* x = (const float*)d_in[0];
    const float* W = (const float*)d_in[1];
    float* out = (float*)d_out;

    const int FSMEM = SMEM_A_FL * 4;   // 119808 B
    cudaFuncSetAttribute(caps_persistent, cudaFuncAttributeMaxDynamicSharedMemorySize, FSMEM);

    int dev = 0, coop = 0;
    cudaGetDevice(&dev);
    cudaDeviceGetAttribute(&coop, cudaDevAttrCooperativeLaunch, dev);

    bool done = false;
    if (coop) {
        void* args[] = {(void*)&x, (void*)&W, (void*)&out};
        cudaError_t e = cudaLaunchCooperativeKernel(
            (void*)caps_persistent, dim3(ISPLIT), dim3(NTHR), args, (size_t)FSMEM,
            (cudaStream_t)0);
        if (e == cudaSuccess) done = true;
        else cudaGetLastError();   // clear, fall back
    }

    if (!done) {
        cudaFuncSetAttribute(fA_k, cudaFuncAttributeMaxDynamicSharedMemorySize, FSMEM);
        cudaFuncSetAttribute(fB_k, cudaFuncAttributeMaxDynamicSharedMemorySize, 57344);
        transpose_k<<<ISPLIT, NTHR, 4352>>>(x);
        fB_k<<<ISPLIT, NTHR, 57344>>>(W, 1);
        squash_k<<<80, NTHR, 4352>>>(out, 0);
        fA_k<<<ISPLIT, NTHR, FSMEM>>>(W, 1);
        fB_k<<<ISPLIT, NTHR, 57344>>>(W, 0);
        squash_k<<<80, NTHR, 4352>>>(out, 0);
        fA_k<<<ISPLIT, NTHR, FSMEM>>>(W, 2);
        fB_k<<<ISPLIT, NTHR, 57344>>>(W, 0);
        squash_k<<<80, NTHR, 4352>>>(out, 1);
    }
}

// round 14
// speedup vs baseline: 1.1566x; 1.1566x over previous
#include <cuda_runtime.h>
#include <cstdint>

#define IN_NODES  1152
#define OUT_NODES 10
#define IN_DIM    8
#define OUT_DIM   16
#define BATCH     256
#define COLS      160
#define KTOT      (IN_NODES * IN_DIM)     // 9216
#define ISPLIT    144
#define CPB       8
#define NTHR      512

typedef unsigned long long u64;

#define FMA2(acc, a, b) asm("fma.rn.f32x2 %0, %1, %2, %0;" : "+l"(acc) : "l"(a), "l"(b))

__device__ __forceinline__ float f2sum(u64 d) {
    float lo, hi;
    asm("mov.b64 {%0,%1}, %2;" : "=f"(lo), "=f"(hi) : "l"(d));
    return lo + hi;
}
__device__ __forceinline__ u64 fpack(float lo, float hi) {
    u64 p;
    asm("mov.b64 %0, {%1,%2};" : "=l"(p) : "f"(lo), "f"(hi));
    return p;
}
__device__ __forceinline__ void cpa16(uint32_t dst, const float* src) {
    asm volatile("cp.async.cg.shared.global [%0], [%1], 16;" :: "r"(dst), "l"(src));
}
#define CPA_COMMIT() asm volatile("cp.async.commit_group;")

// Wait for stream predecessor (PDL). No-op when launched without the PDL attribute.
__device__ __forceinline__ void pdl_wait() {
#if __CUDA_ARCH__ >= 900
    cudaGridDependencySynchronize();
#endif
}

// ---------------- device scratch ----------------
__device__ float g_xT   [KTOT * BATCH];            // x transposed [ik][b]
__device__ float g_spart[ISPLIT * COLS * BATCH];   // s partials [grp][col][b]
__device__ float g_vT2  [COLS * BATCH];            // v col-major [col][b]
__device__ float g_b    [IN_NODES * OUT_NODES];    // routing logits

// Phase-A smem float offsets (double-buffered)
#define VS0 0
#define XS0 10880
#define VS1 14976
#define XS1 25856
#define SMEM_FL 29952

// ---------------- transpose x [256][9216] -> xT [9216][256] ----------------
__global__ void transpose_x_kernel(const float* __restrict__ x) {
    __shared__ float tile[32][33];
    int ik0 = blockIdx.x * 32;
    int b0  = blockIdx.y * 32;
    int tx = threadIdx.x, ty = threadIdx.y;
#pragma unroll
    for (int r = 0; r < 32; r += 8)
        tile[ty + r][tx] = x[(size_t)(b0 + ty + r) * KTOT + ik0 + tx];
    __syncthreads();
#pragma unroll
    for (int r = 0; r < 32; r += 8)
        g_xT[(size_t)(ik0 + ty + r) * BATCH + b0 + tx] = tile[tx][ty + r];
}

// stage one phase-A chunk (64 b): vs[160][68] + xs[64][64], 3584 x cp.async.16
__device__ __forceinline__ void stageA(int cb, uint32_t vsa, uint32_t xsa, int i0, int tid) {
    const int b0 = cb * 64;
    for (int it = tid; it < 3584; it += NTHR) {
        if (it < 2560) {
            int col = it >> 4, q = (it & 15) << 2;
            cpa16(vsa + (col * 68 + q) * 4, g_vT2 + col * BATCH + b0 + q);
        } else {
            int r = it - 2560;
            int row = r >> 4, q = (r & 15) << 2;
            cpa16(xsa + (row * 64 + q) * 4, g_xT + ((size_t)(i0 * 8) + row) * BATCH + b0 + q);
        }
    }
    CPA_COMMIT();
}

// prefetch one phase-B chunk into regs (k-pair packing)
__device__ __forceinline__ void loadB(u64* pf, int ch, int i0, int tid) {
    const int b0 = ch * 64;
#pragma unroll
    for (int r = 0; r < 4; ++r) {
        int it = tid + NTHR * r;
        int ic2 = it >> 8, kp = (it >> 6) & 3, b = it & 63;
        const float* gp = g_xT + ((size_t)(i0 + ic2) * 8 + 2 * kp) * BATCH + b0 + b;
        pf[r] = fpack(gp[0], gp[BATCH]);
    }
}

// ---------------- fused: b-update + softmax + s-GEMM (R10 body + PDL entry) ----------------
__global__ __launch_bounds__(NTHR, 1) void f_kernel(const float* __restrict__ W, int mode) {
    extern __shared__ float sm[];
    __shared__ float bsA[2][80];
    __shared__ float brow[80];
    __shared__ float cs[80];

    pdl_wait();

    const int i0  = blockIdx.x * CPB;
    const int tid = threadIdx.x;
    const uint32_t smb = (uint32_t)__cvta_generic_to_shared(sm);

    if (mode > 0) {
        // ===== Phase A: T[i,k,col] = sum_b xT[ik,b]*vT2[col,b]; double-buffered =====
        const int w = tid >> 5, lane = tid & 31;
        const int ic = w & 7, bh = w >> 3;

        u64 acc2[8][5];
#pragma unroll
        for (int kk = 0; kk < 8; ++kk)
#pragma unroll
            for (int cc = 0; cc < 5; ++cc) acc2[kk][cc] = 0ULL;

        stageA(0, smb + VS0 * 4, smb + XS0 * 4, i0, tid);
        stageA(1, smb + VS1 * 4, smb + XS1 * 4, i0, tid);

#pragma unroll
        for (int cb = 0; cb < 4; ++cb) {
            if (cb < 3) asm volatile("cp.async.wait_group 1;");
            else        asm volatile("cp.async.wait_group 0;");
            __syncthreads();

            const float* vsb = sm + ((cb & 1) ? VS1 : VS0);
            const float* xsb = sm + ((cb & 1) ? XS1 : XS0);
            const float* vbase = vsb + lane * 68 + bh * 32;
            const float* xbase = xsb + ic * 512 + bh * 32;

#pragma unroll
            for (int b4 = 0; b4 < 8; ++b4) {
                ulonglong2 vvx[5];
#pragma unroll
                for (int cc = 0; cc < 5; ++cc)
                    vvx[cc] = *(const ulonglong2*)(vbase + cc * 2176 + 4 * b4);
#pragma unroll
                for (int kk = 0; kk < 8; ++kk) {
                    ulonglong2 xv = *(const ulonglong2*)(xbase + kk * 64 + 4 * b4);
#pragma unroll
                    for (int cc = 0; cc < 5; ++cc) {
                        FMA2(acc2[kk][cc], xv.x, vvx[cc].x);
                        FMA2(acc2[kk][cc], xv.y, vvx[cc].y);
                    }
                }
            }

            if (cb < 2) {
                __syncthreads();
                stageA(cb + 2, smb + ((cb & 1) ? VS1 : VS0) * 4,
                               smb + ((cb & 1) ? XS1 : XS0) * 4, i0, tid);
            }
        }

        // contract with W -> delta-b partials; shfl reduce over 16-lane j groups
#pragma unroll
        for (int cc = 0; cc < 5; ++cc) {
            int col = cc * 32 + lane;
            const float4* w4 = (const float4*)(W + ((size_t)(i0 + ic) * 160 + col) * 8);
            float4 wa = w4[0], wb = w4[1];
            float p = wa.x * f2sum(acc2[0][cc]) + wa.y * f2sum(acc2[1][cc])
                    + wa.z * f2sum(acc2[2][cc]) + wa.w * f2sum(acc2[3][cc])
                    + wb.x * f2sum(acc2[4][cc]) + wb.y * f2sum(acc2[5][cc])
                    + wb.z * f2sum(acc2[6][cc]) + wb.w * f2sum(acc2[7][cc]);
#pragma unroll
            for (int off = 8; off; off >>= 1)
                p += __shfl_xor_sync(0xffffffffu, p, off, 16);
            if ((lane & 15) == 0)
                bsA[bh][ic * 10 + cc * 2 + (lane >> 4)] = p;
        }
        __syncthreads();

        if (tid < 80) {
            float bn = (bsA[0][tid] + bsA[1][tid]) * (1.0f / (float)BATCH);
            if (mode == 2) bn += g_b[i0 * OUT_NODES + tid];
            g_b[i0 * OUT_NODES + tid] = bn;
            brow[tid] = bn;
        }
        __syncthreads();
        if (tid < 8) {
            float m = -1e30f;
#pragma unroll
            for (int j = 0; j < 10; ++j) m = fmaxf(m, brow[tid * 10 + j]);
            float e[10], s = 0.0f;
#pragma unroll
            for (int j = 0; j < 10; ++j) { e[j] = __expf(brow[tid * 10 + j] - m); s += e[j]; }
            float inv = 1.0f / s;
#pragma unroll
            for (int j = 0; j < 10; ++j) cs[tid * 10 + j] = e[j] * inv;
        }
        __syncthreads();
    }

    // ===== Phase B: spart = sum_{ic,k} (c*W)[i,col,k]*xT[ik,b]; reg double-buffer =====
    float* ws = sm;                     // [8 ic][160 col][8 k] scaled W
    u64*   xb = (u64*)(sm + 10240);     // [8 ic][4 kp][64 b]
    const int tx = tid & 15;
    const int ty = tid >> 4;            // 0..31, 5 cols each

    u64 pf[4];
    loadB(pf, 0, i0, tid);

    for (int ch = 0; ch < 4; ++ch) {
        const int b0 = ch * 64;
        __syncthreads();
        if (ch == 0) {
            const float4* W4 = (const float4*)(W + (size_t)i0 * 1280);
            float4* ws4 = (float4*)ws;
            for (int q = tid; q < 2560; q += NTHR) {
                int ic2 = q / 320, r = q - ic2 * 320;
                float c = (mode == 0) ? 0.1f : cs[ic2 * 10 + (r >> 5)];
                float4 wv = W4[q];
                ws4[q] = make_float4(wv.x * c, wv.y * c, wv.z * c, wv.w * c);
            }
        }
#pragma unroll
        for (int r = 0; r < 4; ++r)
            xb[tid + NTHR * r] = pf[r];
        __syncthreads();
        if (ch < 3) loadB(pf, ch + 1, i0, tid);

        u64 accB[4][5];
#pragma unroll
        for (int q = 0; q < 4; ++q)
#pragma unroll
            for (int cc = 0; cc < 5; ++cc) accB[q][cc] = 0ULL;

        const float* wrow = ws + ty * 40;
#pragma unroll 2
        for (int ic2 = 0; ic2 < CPB; ++ic2) {
#pragma unroll
            for (int kph = 0; kph < 2; ++kph) {
                ulonglong2 wx[5];
#pragma unroll
                for (int cc = 0; cc < 5; ++cc)
                    wx[cc] = *(const ulonglong2*)(wrow + ic2 * 1280 + cc * 8 + kph * 4);
#pragma unroll
                for (int kpl = 0; kpl < 2; ++kpl) {
                    const u64* xp = xb + (ic2 * 4 + kph * 2 + kpl) * 64 + tx;
                    u64 x0 = xp[0], x1 = xp[16], x2 = xp[32], x3 = xp[48];
#pragma unroll
                    for (int cc = 0; cc < 5; ++cc) {
                        u64 w2 = kpl ? wx[cc].y : wx[cc].x;
                        FMA2(accB[0][cc], x0, w2);
                        FMA2(accB[1][cc], x1, w2);
                        FMA2(accB[2][cc], x2, w2);
                        FMA2(accB[3][cc], x3, w2);
                    }
                }
            }
        }

        float* outp = g_spart + (size_t)blockIdx.x * (COLS * BATCH) + b0 + tx;
#pragma unroll
        for (int cc = 0; cc < 5; ++cc) {
            int col = ty * 5 + cc;
#pragma unroll
            for (int q = 0; q < 4; ++q)
                outp[col * BATCH + 16 * q] = f2sum(accB[q][cc]);
        }
    }
}

// ---------------- squash: reduce 144 partials, write vT2 (+out), coalesced ----------------
__global__ __launch_bounds__(256) void squash_kernel(float* __restrict__ out, int write_out) {
    __shared__ float red[16][16][17];

    pdl_wait();

    const int j  = blockIdx.x;
    const int b0 = blockIdx.y * 16;
    const int tid = threadIdx.x;
    const int b_loc = tid & 15, isg = tid >> 4;

    float acc[16];
#pragma unroll
    for (int d = 0; d < 16; ++d) acc[d] = 0.0f;
    for (int t = 0; t < 9; ++t) {
        int is = isg * 9 + t;
        const float* p = g_spart + ((size_t)is * COLS + j * 16) * BATCH + b0 + b_loc;
#pragma unroll
        for (int d = 0; d < 16; ++d) acc[d] += p[d * BATCH];
    }
#pragma unroll
    for (int d = 0; d < 16; ++d) red[isg][d][b_loc] = acc[d];
    __syncthreads();

    const int b2 = tid >> 4, d2 = tid & 15;
    float sv = 0.0f;
#pragma unroll
    for (int g = 0; g < 16; ++g) sv += red[g][d2][b2];

    float sq = sv * sv;
#pragma unroll
    for (int off = 8; off; off >>= 1)
        sq += __shfl_xor_sync(0xffffffffu, sq, off, 16);
    float coef = sq * rsqrtf(sq) / (1.0f + sq);
    float v = sv * coef;

    if (write_out)
        out[(size_t)(b0 + b2) * COLS + j * 16 + d2] = v;

    __syncthreads();
    red[0][d2][b2] = v;
    __syncthreads();
    const int d2n = tid >> 4, b2n = tid & 15;
    g_vT2[(size_t)(j * 16 + d2n) * BATCH + b0 + b2n] = red[0][d2n][b2n];
}

// ---------------- launch sequence: PDL-chained, with plain fallback ----------------
template <typename K, typename... Args>
static inline bool launch_pdl(K kern, dim3 g, dim3 b, size_t smem, Args... args) {
    cudaLaunchConfig_t cfg = {};
    cfg.gridDim = g; cfg.blockDim = b; cfg.dynamicSmemBytes = smem;
    cfg.stream = (cudaStream_t)0;
    cudaLaunchAttribute attr[1];
    attr[0].id = cudaLaunchAttributeProgrammaticStreamSerialization;
    attr[0].val.programmaticStreamSerializationAllowed = 1;
    cfg.attrs = attr; cfg.numAttrs = 1;
    return cudaLaunchKernelEx(&cfg, kern, args...) == cudaSuccess;
}

extern "C" void kernel_launch(void* const* d_in, const int* in_sizes, int n_in,
                              void* d_out, int out_size) {
    const float* x = (const float*)d_in[0];
    const float* W = (const float*)d_in[1];
    float* out = (float*)d_out;

    const int FSMEM = SMEM_FL * 4;   // 119808 B
    cudaFuncSetAttribute(f_kernel, cudaFuncAttributeMaxDynamicSharedMemorySize, FSMEM);

    transpose_x_kernel<<<dim3(KTOT / 32, BATCH / 32), dim3(32, 8)>>>(x);

    bool ok = true;
    ok = ok && launch_pdl(f_kernel, dim3(ISPLIT), dim3(NTHR), (size_t)FSMEM, W, 0);
    ok = ok && launch_pdl(squash_kernel, dim3(10, 16), dim3(256), (size_t)0, out, 0);
    ok = ok && launch_pdl(f_kernel, dim3(ISPLIT), dim3(NTHR), (size_t)FSMEM, W, 1);
    ok = ok && launch_pdl(squash_kernel, dim3(10, 16), dim3(256), (size_t)0, out, 0);
    ok = ok && launch_pdl(f_kernel, dim3(ISPLIT), dim3(NTHR), (size_t)FSMEM, W, 2);
    ok = ok && launch_pdl(squash_kernel, dim3(10, 16), dim3(256), (size_t)0, out, 1);

    if (!ok) {
        // PDL unsupported in this context: clear error, re-issue plain (stream order
        // makes the partial PDL prefix + full plain sequence still correct: every
        // kernel is deterministic and idempotent given its stream predecessors).
        cudaGetLastError();
        f_kernel<<<ISPLIT, NTHR, FSMEM>>>(W, 0);
        squash_kernel<<<dim3(10, 16), 256>>>(out, 0);
        f_kernel<<<ISPLIT, NTHR, FSMEM>>>(W, 1);
        squash_kernel<<<dim3(10, 16), 256>>>(out, 0);
        f_kernel<<<ISPLIT, NTHR, FSMEM>>>(W, 2);
        squash_kernel<<<dim3(10, 16), 256>>>(out, 1);
    }
}

// round 15
// speedup vs baseline: 1.1714x; 1.0128x over previous
#include <cuda_runtime.h>
#include <cstdint>

#define IN_NODES  1152
#define OUT_NODES 10
#define IN_DIM    8
#define OUT_DIM   16
#define BATCH     256
#define COLS      160
#define KTOT      (IN_NODES * IN_DIM)     // 9216
#define ISPLIT    144
#define CPB       8
#define NTHR      512

typedef unsigned long long u64;

#define FMA2(acc, a, b) asm("fma.rn.f32x2 %0, %1, %2, %0;" : "+l"(acc) : "l"(a), "l"(b))

__device__ __forceinline__ float f2sum(u64 d) {
    float lo, hi;
    asm("mov.b64 {%0,%1}, %2;" : "=f"(lo), "=f"(hi) : "l"(d));
    return lo + hi;
}
__device__ __forceinline__ float2 f2unpack(u64 d) {
    float2 r;
    asm("mov.b64 {%0,%1}, %2;" : "=f"(r.x), "=f"(r.y) : "l"(d));
    return r;
}
__device__ __forceinline__ u64 fpack(float lo, float hi) {
    u64 p;
    asm("mov.b64 %0, {%1,%2};" : "=l"(p) : "f"(lo), "f"(hi));
    return p;
}
__device__ __forceinline__ void cpa16(uint32_t dst, const float* src) {
    asm volatile("cp.async.cg.shared.global [%0], [%1], 16;" :: "r"(dst), "l"(src));
}
#define CPA_COMMIT() asm volatile("cp.async.commit_group;")

__device__ __forceinline__ void pdl_wait() {
#if __CUDA_ARCH__ >= 900
    cudaGridDependencySynchronize();
#endif
}

// ---------------- device scratch ----------------
__device__ float g_xT   [KTOT * BATCH];            // x transposed [ik][b] (written by f0)
__device__ float g_spart[ISPLIT * COLS * BATCH];   // s partials [grp][col][b]
__device__ float g_vT2  [COLS * BATCH];            // v col-major [col][b]
__device__ float g_b    [IN_NODES * OUT_NODES];    // routing logits

// f_kernel phase-A smem float offsets (double-buffered)
#define VS0 0
#define XS0 10880
#define VS1 14976
#define XS1 25856
#define SMEM_FL 29952

// =========================================================================
// f0: iteration-1 s-GEMM (c = 0.1), staged DIRECTLY from x; also emits g_xT.
// xb rows padded to 66 u64 (STS conflict mitigation); xp loads stay 1-wf.
// =========================================================================

// prefetch one chunk: 1024 float4, coalesced rows of x
__device__ __forceinline__ void loadBX(float4* pf, int ch, const float* __restrict__ x,
                                       int bid, int tid) {
    const int b0 = ch * 64;
#pragma unroll
    for (int r = 0; r < 2; ++r) {
        int id = tid + NTHR * r;
        int b = id >> 4, q = id & 15;
        pf[r] = *(const float4*)(x + (size_t)(b0 + b) * KTOT + bid * 64 + q * 4);
    }
}

__global__ __launch_bounds__(NTHR, 1) void f0_kernel(const float* __restrict__ x,
                                                     const float* __restrict__ W) {
    extern __shared__ float sm[];
    float* ws = sm;                     // [8 ic][160 col][8 k] scaled W (c = 0.1)
    u64*   xb = (u64*)(sm + 10240);     // [32 rows][66] u64 k-pairs
    const int i0  = blockIdx.x * CPB;
    const int tid = threadIdx.x;
    const int tx = tid & 15;
    const int ty = tid >> 4;            // 0..31, 5 cols each

    float4 pf[2];
    loadBX(pf, 0, x, blockIdx.x, tid);

    for (int ch = 0; ch < 4; ++ch) {
        const int b0 = ch * 64;
        __syncthreads();
        if (ch == 0) {
            const float4* W4 = (const float4*)(W + (size_t)i0 * 1280);
            float4* ws4 = (float4*)ws;
            for (int q = tid; q < 2560; q += NTHR) {
                float4 wv = W4[q];
                ws4[q] = make_float4(wv.x * 0.1f, wv.y * 0.1f, wv.z * 0.1f, wv.w * 0.1f);
            }
        }
        // STS: float4 -> two u64 k-pairs at (ic2*4+kp) row, col b
#pragma unroll
        for (int r = 0; r < 2; ++r) {
            int id = tid + NTHR * r;
            int b = id >> 4, q = id & 15;
            int ic2 = q >> 1, kp0 = (q & 1) * 2;
            xb[(ic2 * 4 + kp0) * 66 + b]     = fpack(pf[r].x, pf[r].y);
            xb[(ic2 * 4 + kp0 + 1) * 66 + b] = fpack(pf[r].z, pf[r].w);
        }
        __syncthreads();
        if (ch < 3) loadBX(pf, ch + 1, x, blockIdx.x, tid);

        // emit g_xT for this chunk (side product for fA/fB of later iterations)
#pragma unroll
        for (int r = 0; r < 4; ++r) {
            int idx = tid + NTHR * r;
            int row = idx >> 6, bb = idx & 63;
            float2 f = f2unpack(xb[row * 66 + bb]);
            int ik = i0 * 8 + (row >> 2) * 8 + (row & 3) * 2;
            g_xT[(size_t)ik * BATCH + b0 + bb]       = f.x;
            g_xT[(size_t)(ik + 1) * BATCH + b0 + bb] = f.y;
        }

        u64 accB[4][5];
#pragma unroll
        for (int q = 0; q < 4; ++q)
#pragma unroll
            for (int cc = 0; cc < 5; ++cc) accB[q][cc] = 0ULL;

        const float* wrow = ws + ty * 40;
#pragma unroll 2
        for (int ic2 = 0; ic2 < CPB; ++ic2) {
#pragma unroll
            for (int kph = 0; kph < 2; ++kph) {
                ulonglong2 wx[5];
#pragma unroll
                for (int cc = 0; cc < 5; ++cc)
                    wx[cc] = *(const ulonglong2*)(wrow + ic2 * 1280 + cc * 8 + kph * 4);
#pragma unroll
                for (int kpl = 0; kpl < 2; ++kpl) {
                    const u64* xp = xb + (ic2 * 4 + kph * 2 + kpl) * 66 + tx;
                    u64 x0 = xp[0], x1 = xp[16], x2 = xp[32], x3 = xp[48];
#pragma unroll
                    for (int cc = 0; cc < 5; ++cc) {
                        u64 w2 = kpl ? wx[cc].y : wx[cc].x;
                        FMA2(accB[0][cc], x0, w2);
                        FMA2(accB[1][cc], x1, w2);
                        FMA2(accB[2][cc], x2, w2);
                        FMA2(accB[3][cc], x3, w2);
                    }
                }
            }
        }

        float* outp = g_spart + (size_t)blockIdx.x * (COLS * BATCH) + b0 + tx;
#pragma unroll
        for (int cc = 0; cc < 5; ++cc) {
            int col = ty * 5 + cc;
#pragma unroll
            for (int q = 0; q < 4; ++q)
                outp[col * BATCH + 16 * q] = f2sum(accB[q][cc]);
        }
    }
}

// =========================================================================
// f_kernel (modes 1,2): b-update + softmax + s-GEMM — R14 body, phase A
// kk-loop split into 2 halves with 4 hoisted xv loads each (load batching).
// =========================================================================

__device__ __forceinline__ void stageA(int cb, uint32_t vsa, uint32_t xsa, int i0, int tid) {
    const int b0 = cb * 64;
    for (int it = tid; it < 3584; it += NTHR) {
        if (it < 2560) {
            int col = it >> 4, q = (it & 15) << 2;
            cpa16(vsa + (col * 68 + q) * 4, g_vT2 + col * BATCH + b0 + q);
        } else {
            int r = it - 2560;
            int row = r >> 4, q = (r & 15) << 2;
            cpa16(xsa + (row * 64 + q) * 4, g_xT + ((size_t)(i0 * 8) + row) * BATCH + b0 + q);
        }
    }
    CPA_COMMIT();
}

__device__ __forceinline__ void loadB(u64* pf, int ch, int i0, int tid) {
    const int b0 = ch * 64;
#pragma unroll
    for (int r = 0; r < 4; ++r) {
        int it = tid + NTHR * r;
        int ic2 = it >> 8, kp = (it >> 6) & 3, b = it & 63;
        const float* gp = g_xT + ((size_t)(i0 + ic2) * 8 + 2 * kp) * BATCH + b0 + b;
        pf[r] = fpack(gp[0], gp[BATCH]);
    }
}

__global__ __launch_bounds__(NTHR, 1) void f_kernel(const float* __restrict__ W, int mode) {
    extern __shared__ float sm[];
    __shared__ float bsA[2][80];
    __shared__ float brow[80];
    __shared__ float cs[80];

    pdl_wait();

    const int i0  = blockIdx.x * CPB;
    const int tid = threadIdx.x;
    const uint32_t smb = (uint32_t)__cvta_generic_to_shared(sm);

    // ===== Phase A: T[i,k,col] = sum_b xT[ik,b]*vT2[col,b]; double-buffered =====
    {
        const int w = tid >> 5, lane = tid & 31;
        const int ic = w & 7, bh = w >> 3;

        u64 acc2[8][5];
#pragma unroll
        for (int kk = 0; kk < 8; ++kk)
#pragma unroll
            for (int cc = 0; cc < 5; ++cc) acc2[kk][cc] = 0ULL;

        stageA(0, smb + VS0 * 4, smb + XS0 * 4, i0, tid);
        stageA(1, smb + VS1 * 4, smb + XS1 * 4, i0, tid);

#pragma unroll
        for (int cb = 0; cb < 4; ++cb) {
            if (cb < 3) asm volatile("cp.async.wait_group 1;");
            else        asm volatile("cp.async.wait_group 0;");
            __syncthreads();

            const float* vsb = sm + ((cb & 1) ? VS1 : VS0);
            const float* xsb = sm + ((cb & 1) ? XS1 : XS0);
            const float* vbase = vsb + lane * 68 + bh * 32;
            const float* xbase = xsb + ic * 512 + bh * 32;

#pragma unroll
            for (int b4 = 0; b4 < 8; ++b4) {
                ulonglong2 vvx[5];
#pragma unroll
                for (int cc = 0; cc < 5; ++cc)
                    vvx[cc] = *(const ulonglong2*)(vbase + cc * 2176 + 4 * b4);
#pragma unroll
                for (int kh = 0; kh < 2; ++kh) {
                    // batch 4 xv loads, then 40 FMA2
                    ulonglong2 xv[4];
#pragma unroll
                    for (int kk = 0; kk < 4; ++kk)
                        xv[kk] = *(const ulonglong2*)(xbase + (kh * 4 + kk) * 64 + 4 * b4);
#pragma unroll
                    for (int kk = 0; kk < 4; ++kk)
#pragma unroll
                        for (int cc = 0; cc < 5; ++cc) {
                            FMA2(acc2[kh * 4 + kk][cc], xv[kk].x, vvx[cc].x);
                            FMA2(acc2[kh * 4 + kk][cc], xv[kk].y, vvx[cc].y);
                        }
                }
            }

            if (cb < 2) {
                __syncthreads();
                stageA(cb + 2, smb + ((cb & 1) ? VS1 : VS0) * 4,
                               smb + ((cb & 1) ? XS1 : XS0) * 4, i0, tid);
            }
        }

        // contract with W -> delta-b partials; shfl reduce over 16-lane j groups
#pragma unroll
        for (int cc = 0; cc < 5; ++cc) {
            int col = cc * 32 + lane;
            const float4* w4 = (const float4*)(W + ((size_t)(i0 + ic) * 160 + col) * 8);
            float4 wa = w4[0], wb = w4[1];
            float p = wa.x * f2sum(acc2[0][cc]) + wa.y * f2sum(acc2[1][cc])
                    + wa.z * f2sum(acc2[2][cc]) + wa.w * f2sum(acc2[3][cc])
                    + wb.x * f2sum(acc2[4][cc]) + wb.y * f2sum(acc2[5][cc])
                    + wb.z * f2sum(acc2[6][cc]) + wb.w * f2sum(acc2[7][cc]);
#pragma unroll
            for (int off = 8; off; off >>= 1)
                p += __shfl_xor_sync(0xffffffffu, p, off, 16);
            if ((lane & 15) == 0)
                bsA[bh][ic * 10 + cc * 2 + (lane >> 4)] = p;
        }
        __syncthreads();

        if (tid < 80) {
            float bn = (bsA[0][tid] + bsA[1][tid]) * (1.0f / (float)BATCH);
            if (mode == 2) bn += g_b[i0 * OUT_NODES + tid];
            g_b[i0 * OUT_NODES + tid] = bn;
            brow[tid] = bn;
        }
        __syncthreads();
        if (tid < 8) {
            float m = -1e30f;
#pragma unroll
            for (int j = 0; j < 10; ++j) m = fmaxf(m, brow[tid * 10 + j]);
            float e[10], s = 0.0f;
#pragma unroll
            for (int j = 0; j < 10; ++j) { e[j] = __expf(brow[tid * 10 + j] - m); s += e[j]; }
            float inv = 1.0f / s;
#pragma unroll
            for (int j = 0; j < 10; ++j) cs[tid * 10 + j] = e[j] * inv;
        }
        __syncthreads();
    }

    // ===== Phase B: spart = sum_{ic,k} (c*W)[i,col,k]*xT[ik,b]; reg double-buffer =====
    float* ws = sm;                     // [8 ic][160 col][8 k] scaled W
    u64*   xb = (u64*)(sm + 10240);     // [8 ic][4 kp][64 b]
    const int tx = tid & 15;
    const int ty = tid >> 4;            // 0..31, 5 cols each

    u64 pf[4];
    loadB(pf, 0, i0, tid);

    for (int ch = 0; ch < 4; ++ch) {
        const int b0 = ch * 64;
        __syncthreads();
        if (ch == 0) {
            const float4* W4 = (const float4*)(W + (size_t)i0 * 1280);
            float4* ws4 = (float4*)ws;
            for (int q = tid; q < 2560; q += NTHR) {
                int ic2 = q / 320, r = q - ic2 * 320;
                float c = cs[ic2 * 10 + (r >> 5)];
                float4 wv = W4[q];
                ws4[q] = make_float4(wv.x * c, wv.y * c, wv.z * c, wv.w * c);
            }
        }
#pragma unroll
        for (int r = 0; r < 4; ++r)
            xb[tid + NTHR * r] = pf[r];
        __syncthreads();
        if (ch < 3) loadB(pf, ch + 1, i0, tid);

        u64 accB[4][5];
#pragma unroll
        for (int q = 0; q < 4; ++q)
#pragma unroll
            for (int cc = 0; cc < 5; ++cc) accB[q][cc] = 0ULL;

        const float* wrow = ws + ty * 40;
#pragma unroll 2
        for (int ic2 = 0; ic2 < CPB; ++ic2) {
#pragma unroll
            for (int kph = 0; kph < 2; ++kph) {
                ulonglong2 wx[5];
#pragma unroll
                for (int cc = 0; cc < 5; ++cc)
                    wx[cc] = *(const ulonglong2*)(wrow + ic2 * 1280 + cc * 8 + kph * 4);
#pragma unroll
                for (int kpl = 0; kpl < 2; ++kpl) {
                    const u64* xp = xb + (ic2 * 4 + kph * 2 + kpl) * 64 + tx;
                    u64 x0 = xp[0], x1 = xp[16], x2 = xp[32], x3 = xp[48];
#pragma unroll
                    for (int cc = 0; cc < 5; ++cc) {
                        u64 w2 = kpl ? wx[cc].y : wx[cc].x;
                        FMA2(accB[0][cc], x0, w2);
                        FMA2(accB[1][cc], x1, w2);
                        FMA2(accB[2][cc], x2, w2);
                        FMA2(accB[3][cc], x3, w2);
                    }
                }
            }
        }

        float* outp = g_spart + (size_t)blockIdx.x * (COLS * BATCH) + b0 + tx;
#pragma unroll
        for (int cc = 0; cc < 5; ++cc) {
            int col = ty * 5 + cc;
#pragma unroll
            for (int q = 0; q < 4; ++q)
                outp[col * BATCH + 16 * q] = f2sum(accB[q][cc]);
        }
    }
}

// ---------------- squash: reduce 144 partials, write vT2 (+out), coalesced ----------------
__global__ __launch_bounds__(256) void squash_kernel(float* __restrict__ out, int write_out) {
    __shared__ float red[16][16][17];

    pdl_wait();

    const int j  = blockIdx.x;
    const int b0 = blockIdx.y * 16;
    const int tid = threadIdx.x;
    const int b_loc = tid & 15, isg = tid >> 4;

    float acc[16];
#pragma unroll
    for (int d = 0; d < 16; ++d) acc[d] = 0.0f;
    for (int t = 0; t < 9; ++t) {
        int is = isg * 9 + t;
        const float* p = g_spart + ((size_t)is * COLS + j * 16) * BATCH + b0 + b_loc;
#pragma unroll
        for (int d = 0; d < 16; ++d) acc[d] += p[d * BATCH];
    }
#pragma unroll
    for (int d = 0; d < 16; ++d) red[isg][d][b_loc] = acc[d];
    __syncthreads();

    const int b2 = tid >> 4, d2 = tid & 15;
    float sv = 0.0f;
#pragma unroll
    for (int g = 0; g < 16; ++g) sv += red[g][d2][b2];

    float sq = sv * sv;
#pragma unroll
    for (int off = 8; off; off >>= 1)
        sq += __shfl_xor_sync(0xffffffffu, sq, off, 16);
    float coef = sq * rsqrtf(sq) / (1.0f + sq);
    float v = sv * coef;

    if (write_out)
        out[(size_t)(b0 + b2) * COLS + j * 16 + d2] = v;

    __syncthreads();
    red[0][d2][b2] = v;
    __syncthreads();
    const int d2n = tid >> 4, b2n = tid & 15;
    g_vT2[(size_t)(j * 16 + d2n) * BATCH + b0 + b2n] = red[0][d2n][b2n];
}

// ---------------- launch sequence: 6 nodes, PDL-chained, plain fallback ----------------
template <typename K, typename... Args>
static inline bool launch_pdl(K kern, dim3 g, dim3 b, size_t smem, Args... args) {
    cudaLaunchConfig_t cfg = {};
    cfg.gridDim = g; cfg.blockDim = b; cfg.dynamicSmemBytes = smem;
    cfg.stream = (cudaStream_t)0;
    cudaLaunchAttribute attr[1];
    attr[0].id = cudaLaunchAttributeProgrammaticStreamSerialization;
    attr[0].val.programmaticStreamSerializationAllowed = 1;
    cfg.attrs = attr; cfg.numAttrs = 1;
    return cudaLaunchKernelEx(&cfg, kern, args...) == cudaSuccess;
}

extern "C" void kernel_launch(void* const* d_in, const int* in_sizes, int n_in,
                              void* d_out, int out_size) {
    const float* x = (const float*)d_in[0];
    const float* W = (const float*)d_in[1];
    float* out = (float*)d_out;

    const int FSMEM  = SMEM_FL * 4;      // 119808 B (f_kernel)
    const int FSMEM0 = 14464 * 4;        // 57856 B (f0: ws + xb[32][66])
    cudaFuncSetAttribute(f_kernel,  cudaFuncAttributeMaxDynamicSharedMemorySize, FSMEM);
    cudaFuncSetAttribute(f0_kernel, cudaFuncAttributeMaxDynamicSharedMemorySize, FSMEM0);

    f0_kernel<<<ISPLIT, NTHR, FSMEM0>>>(x, W);

    bool ok = true;
    ok = ok && launch_pdl(squash_kernel, dim3(10, 16), dim3(256), (size_t)0, out, 0);
    ok = ok && launch_pdl(f_kernel, dim3(ISPLIT), dim3(NTHR), (size_t)FSMEM, W, 1);
    ok = ok && launch_pdl(squash_kernel, dim3(10, 16), dim3(256), (size_t)0, out, 0);
    ok = ok && launch_pdl(f_kernel, dim3(ISPLIT), dim3(NTHR), (size_t)FSMEM, W, 2);
    ok = ok && launch_pdl(squash_kernel, dim3(10, 16), dim3(256), (size_t)0, out, 1);

    if (!ok) {
        cudaGetLastError();
        squash_kernel<<<dim3(10, 16), 256>>>(out, 0);
        f_kernel<<<ISPLIT, NTHR, FSMEM>>>(W, 1);
        squash_kernel<<<dim3(10, 16), 256>>>(out, 0);
        f_kernel<<<ISPLIT, NTHR, FSMEM>>>(W, 2);
        squash_kernel<<<dim3(10, 16), 256>>>(out, 1);
    }
}